// round 9
// baseline (speedup 1.0000x reference)
#include <cuda_runtime.h>

#define HW_   1048576   // 1024*1024
#define W_    1024
#define H_    1024
#define NTR_  12

#define SH_   51        // staged rows max (span<=47 + 4 guard)
#define SPW_  56        // staged row pitch: float2 units for smA, floats for sm2
#define NQ_   14

// Output float layout (out_size = 12*4*HW + 144):
//   xs   : [0, 12*3*HW)        (12,3,1024,1024)
//   os   : [12*3*HW, 12*4*HW)  (12,1,1024,1024)
//   z    : [12*4*HW, +72)   inv_z: [+72, +144)

__global__ void __launch_bounds__(256)
sample_tile_kernel(const float* __restrict__ x,
                   const float* __restrict__ A,
                   float* __restrict__ out) {
    __shared__ float2 smA[SH_ * SPW_];   // (ch0, ch1) interleaved
    __shared__ float  sm2[SH_ * SPW_];   // ch2

    const int n   = blockIdx.z;
    const int w0  = blockIdx.x << 5;
    const int h0  = blockIdx.y << 5;
    const int tid = threadIdx.x;

    const float t00 = __ldg(A + n*6 + 0);
    const float t01 = __ldg(A + n*6 + 1);
    const float t02 = __ldg(A + n*6 + 2);
    const float t10 = __ldg(A + n*6 + 3);
    const float t11 = __ldg(A + n*6 + 4);
    const float t12 = __ldg(A + n*6 + 5);

    if (w0 == 0 && h0 == 0 && tid == 0) {
        float* z  = out + (size_t)NTR_ * 4 * HW_ + n * 6;
        float* iz = z + NTR_ * 6;
        z[0] = t00; z[1] = t01; z[2] = t02;
        z[3] = t10; z[4] = t11; z[5] = t12;
        float inv = 1.0f / (t00 * t11 - t01 * t10);
        float ia =  t11 * inv, ib = -t01 * inv;
        float ic = -t10 * inv, id =  t00 * inv;
        iz[0] = ia; iz[1] = ib; iz[2] = -(ia * t02 + ib * t12);
        iz[3] = ic; iz[4] = id; iz[5] = -(ic * t02 + id * t12);
    }

    const float cx = 512.0f * (t02 - t00 - t01 + 1.0f) - 0.5f;
    const float cy = 512.0f * (t12 - t10 - t11 + 1.0f) - 0.5f;

    // Tile-corner preimage bbox (affine -> extremes at corners).
    const float wlo = (float)w0 + 0.5f, whi = (float)w0 + 31.5f;
    const float hlo = (float)h0 + 0.5f, hhi = (float)h0 + 31.5f;
    const float hxl = fmaf(t01, hlo, cx), hxh = fmaf(t01, hhi, cx);
    const float hyl = fmaf(t11, hlo, cy), hyh = fmaf(t11, hhi, cy);

    const float ix00 = fmaf(t00, wlo, hxl), ix01 = fmaf(t00, wlo, hxh);
    const float ix10 = fmaf(t00, whi, hxl), ix11 = fmaf(t00, whi, hxh);
    const float iy00 = fmaf(t10, wlo, hyl), iy01 = fmaf(t10, wlo, hyh);
    const float iy10 = fmaf(t10, whi, hyl), iy11 = fmaf(t10, whi, hyh);

    const float ixmin = fminf(fminf(ix00, ix01), fminf(ix10, ix11));
    const float ixmax = fmaxf(fmaxf(ix00, ix01), fmaxf(ix10, ix11));
    const float iymin = fminf(fminf(iy00, iy01), fminf(iy10, iy11));
    const float iymax = fmaxf(fmaxf(iy00, iy01), fmaxf(iy10, iy11));

    const bool inside  = (ixmin >= 5.0f) & (ixmax <= 1018.0f) &
                         (iymin >= 5.0f) & (iymax <= 1018.0f);
    const bool outside = (ixmax < -1.002f) | (ixmin > 1024.002f) |
                         (iymax < -1.002f) | (iymin > 1024.002f);

    const int tx = tid & 31;
    const int ty = tid >> 5;

    float* xs0 = out + (size_t)n * 3 * HW_;
    float* xs1 = xs0 + HW_;
    float* xs2 = xs1 + HW_;
    float* oso = out + (size_t)NTR_ * 3 * HW_ + (size_t)n * HW_;

    if (outside) {
        #pragma unroll
        for (int k = 0; k < 4; ++k) {
            const int h = h0 + ty + (k << 3);
            const size_t o = ((size_t)h << 10) + (w0 + tx);
            xs0[o] = 0.f; xs1[o] = 0.f; xs2[o] = 0.f; oso[o] = 0.f;
        }
        return;
    }

    if (inside) {
        const int xmin = (int)floorf(ixmin) - 1;
        const int ymin = (int)floorf(iymin) - 1;
        const int xq   = xmin & ~3;                      // 16B-aligned
        int Ht = ((int)floorf(iymax) + 2) - ymin + 1;
        Ht = min(Ht, min(SH_, H_ - ymin));
        const int nq = min(NQ_, (W_ - xq) >> 2);

        // ---- stage: 16 rows x 16 quad-lanes; channels 0/1 pair-interleaved
        {
            const int qi = tid & 15;
            if (qi < nq) {
                for (int r = tid >> 4; r < Ht; r += 16) {
                    const float4* src = (const float4*)(x + ((ymin + r) << 10) + xq) + qi;
                    const float4 v0 = __ldg(src);
                    const float4 v1 = __ldg(src +     HW_ / 4);
                    const float4 v2 = __ldg(src + 2 * HW_ / 4);
                    const int d = r * SPW_ + (qi << 2);      // float2 index / float index
                    // two STS.128 carrying 4 interleaved (ch0,ch1) pairs
                    *(float4*)&smA[d]     = make_float4(v0.x, v1.x, v0.y, v1.y);
                    *(float4*)&smA[d + 2] = make_float4(v0.z, v1.z, v0.w, v1.w);
                    *(float4*)&sm2[d]     = v2;
                }
            }
        }
        __syncthreads();

        const float fw = (float)(w0 + tx) + 0.5f;
        #pragma unroll
        for (int k = 0; k < 4; ++k) {
            const int h = h0 + ty + (k << 3);
            const float fh = (float)h + 0.5f;
            const float ix = fmaf(t00, fw, fmaf(t01, fh, cx));
            const float iy = fmaf(t10, fw, fmaf(t11, fh, cy));

            const float x0f = floorf(ix);
            const float y0f = floorf(iy);
            const float wx1 = ix - x0f;
            const float wy1 = iy - y0f;

            const int base = ((int)y0f - ymin) * SPW_ + ((int)x0f - xq);

            // channels 0+1: four LDS.64
            const float2 p00 = smA[base],        p10 = smA[base + 1];
            const float2 p01 = smA[base + SPW_], p11 = smA[base + SPW_ + 1];

            float u0 = fmaf(wx1, p10.x - p00.x, p00.x);
            float u1 = fmaf(wx1, p11.x - p01.x, p01.x);
            const float r0 = fmaf(wy1, u1 - u0, u0);

            u0 = fmaf(wx1, p10.y - p00.y, p00.y);
            u1 = fmaf(wx1, p11.y - p01.y, p01.y);
            const float r1 = fmaf(wy1, u1 - u0, u0);

            // channel 2: four LDS.32
            const float a00 = sm2[base],        a10 = sm2[base + 1];
            const float a01 = sm2[base + SPW_], a11 = sm2[base + SPW_ + 1];
            u0 = fmaf(wx1, a10 - a00, a00);
            u1 = fmaf(wx1, a11 - a01, a01);
            const float r2 = fmaf(wy1, u1 - u0, u0);

            const size_t o = ((size_t)h << 10) + (w0 + tx);
            xs0[o] = r0; xs1[o] = r1; xs2[o] = r2; oso[o] = 1.0f;
        }
        return;
    }

    // ---- boundary tiles: per-pixel clamp + validity path (always correct)
    const float fw = (float)(w0 + tx) + 0.5f;
    #pragma unroll
    for (int k = 0; k < 4; ++k) {
        const int h = h0 + ty + (k << 3);
        const float fh = (float)h + 0.5f;
        const float ix = fmaf(t00, fw, fmaf(t01, fh, cx));
        const float iy = fmaf(t10, fw, fmaf(t11, fh, cy));

        const float x0f = floorf(ix);
        const float y0f = floorf(iy);
        const float wx1 = ix - x0f;
        const float wy1 = iy - y0f;
        const float wx0 = 1.0f - wx1;
        const float wy0 = 1.0f - wy1;

        const int x0 = (int)x0f, y0 = (int)y0f;
        const int x1 = x0 + 1,   y1 = y0 + 1;
        const bool vx0 = ((unsigned)x0 < (unsigned)W_);
        const bool vx1 = ((unsigned)x1 < (unsigned)W_);
        const bool vy0 = ((unsigned)y0 < (unsigned)H_);
        const bool vy1 = ((unsigned)y1 < (unsigned)H_);

        const float m00 = wx0 * wy0 * (float)(vx0 && vy0);
        const float m10 = wx1 * wy0 * (float)(vx1 && vy0);
        const float m01 = wx0 * wy1 * (float)(vx0 && vy1);
        const float m11 = wx1 * wy1 * (float)(vx1 && vy1);

        const int xc0 = min(max(x0, 0), W_ - 1);
        const int xc1 = min(max(x1, 0), W_ - 1);
        const int yc0 = min(max(y0, 0), H_ - 1);
        const int yc1 = min(max(y1, 0), H_ - 1);

        const int o00 = (yc0 << 10) + xc0;
        const int o10 = (yc0 << 10) + xc1;
        const int o01 = (yc1 << 10) + xc0;
        const int o11 = (yc1 << 10) + xc1;

        const float r0 = __ldg(x + o00)         * m00 + __ldg(x + o10)         * m10
                       + __ldg(x + o01)         * m01 + __ldg(x + o11)         * m11;
        const float r1 = __ldg(x + HW_ + o00)   * m00 + __ldg(x + HW_ + o10)   * m10
                       + __ldg(x + HW_ + o01)   * m01 + __ldg(x + HW_ + o11)   * m11;
        const float r2 = __ldg(x + 2*HW_ + o00) * m00 + __ldg(x + 2*HW_ + o10) * m10
                       + __ldg(x + 2*HW_ + o01) * m01 + __ldg(x + 2*HW_ + o11) * m11;

        const size_t o = ((size_t)h << 10) + (w0 + tx);
        xs0[o] = r0; xs1[o] = r1; xs2[o] = r2;
        oso[o] = m00 + m10 + m01 + m11;
    }
}

extern "C" void kernel_launch(void* const* d_in, const int* in_sizes, int n_in,
                              void* d_out, int out_size) {
    const float* x = (const float*)d_in[0];        // (1,3,1024,1024)
    const float* A = (const float*)d_in[1];        // (1,12,2,3)
    float* out = (float*)d_out;

    dim3 grid(W_ / 32, H_ / 32, NTR_);
    sample_tile_kernel<<<grid, 256>>>(x, A, out);
}

// round 10
// speedup vs baseline: 1.3804x; 1.3804x over previous
#include <cuda_runtime.h>
#include <cuda.h>
#include <cstdint>

#define HW_   1048576   // 1024*1024
#define W_    1024
#define H_    1024
#define NTR_  12

#define BOXW_ 56                      // TMA box inner dim (floats) == smem pitch
#define BOXH_ 52                      // TMA box rows
#define PLANE_ (BOXW_ * BOXH_)        // 2912 floats per channel
#define STAGE_BYTES_ (BOXW_ * BOXH_ * 3 * 4)   // 34944

// Output float layout (out_size = 12*4*HW + 144):
//   xs   : [0, 12*3*HW)        (12,3,1024,1024)
//   os   : [12*3*HW, 12*4*HW)  (12,1,1024,1024)
//   z    : [12*4*HW, +72)   inv_z: [+72, +144)

__global__ void __launch_bounds__(256)
sample_tile_tma(const float* __restrict__ x,
                const float* __restrict__ A,
                float* __restrict__ out,
                const __grid_constant__ CUtensorMap tmap) {
    __shared__ alignas(128) float sm[3 * PLANE_];
    __shared__ alignas(8) unsigned long long mbar;

    const int n   = blockIdx.z;
    const int w0  = blockIdx.x << 5;
    const int h0  = blockIdx.y << 5;
    const int tid = threadIdx.x;

    const float t00 = __ldg(A + n*6 + 0);
    const float t01 = __ldg(A + n*6 + 1);
    const float t02 = __ldg(A + n*6 + 2);
    const float t10 = __ldg(A + n*6 + 3);
    const float t11 = __ldg(A + n*6 + 4);
    const float t12 = __ldg(A + n*6 + 5);

    // z / inv_z emission (before any early-exit branch!)
    if (w0 == 0 && h0 == 0 && tid == 0) {
        float* z  = out + (size_t)NTR_ * 4 * HW_ + n * 6;
        float* iz = z + NTR_ * 6;
        z[0] = t00; z[1] = t01; z[2] = t02;
        z[3] = t10; z[4] = t11; z[5] = t12;
        float inv = 1.0f / (t00 * t11 - t01 * t10);
        float ia =  t11 * inv, ib = -t01 * inv;
        float ic = -t10 * inv, id =  t00 * inv;
        iz[0] = ia; iz[1] = ib; iz[2] = -(ia * t02 + ib * t12);
        iz[3] = ic; iz[4] = id; iz[5] = -(ic * t02 + id * t12);
    }

    const float cx = 512.0f * (t02 - t00 - t01 + 1.0f) - 0.5f;
    const float cy = 512.0f * (t12 - t10 - t11 + 1.0f) - 0.5f;

    // Tile-corner preimage bbox (affine -> extremes at corners).
    const float wlo = (float)w0 + 0.5f, whi = (float)w0 + 31.5f;
    const float hlo = (float)h0 + 0.5f, hhi = (float)h0 + 31.5f;
    const float hxl = fmaf(t01, hlo, cx), hxh = fmaf(t01, hhi, cx);
    const float hyl = fmaf(t11, hlo, cy), hyh = fmaf(t11, hhi, cy);

    const float ix00 = fmaf(t00, wlo, hxl), ix01 = fmaf(t00, wlo, hxh);
    const float ix10 = fmaf(t00, whi, hxl), ix11 = fmaf(t00, whi, hxh);
    const float iy00 = fmaf(t10, wlo, hyl), iy01 = fmaf(t10, wlo, hyh);
    const float iy10 = fmaf(t10, whi, hyl), iy11 = fmaf(t10, whi, hyh);

    const float ixmin = fminf(fminf(ix00, ix01), fminf(ix10, ix11));
    const float ixmax = fmaxf(fmaxf(ix00, ix01), fmaxf(ix10, ix11));
    const float iymin = fminf(fminf(iy00, iy01), fminf(iy10, iy11));
    const float iymax = fmaxf(fmaxf(iy00, iy01), fmaxf(iy10, iy11));

    const int tx = tid & 31;
    const int ty = tid >> 5;

    float* xs0 = out + (size_t)n * 3 * HW_;
    float* xs1 = xs0 + HW_;
    float* xs2 = xs1 + HW_;
    float* oso = out + (size_t)NTR_ * 3 * HW_ + (size_t)n * HW_;

    const bool outside = (ixmax < -1.002f) | (ixmin > 1024.002f) |
                         (iymax < -1.002f) | (iymin > 1024.002f);
    if (outside) {
        #pragma unroll
        for (int k = 0; k < 4; ++k) {
            const int h = h0 + ty + (k << 3);
            const size_t o = ((size_t)h << 10) + (w0 + tx);
            xs0[o] = 0.f; xs1[o] = 0.f; xs2[o] = 0.f; oso[o] = 0.f;
        }
        return;
    }

    const int xmin = (int)floorf(ixmin) - 1;
    const int ymin = (int)floorf(iymin) - 1;
    const int xq   = xmin & ~3;            // 16B-aligned (works for negatives)

    // ---- one TMA 3D bulk load stages the whole bbox (OOB auto zero-filled)
    const uint32_t mb = (uint32_t)__cvta_generic_to_shared(&mbar);
    const uint32_t sa = (uint32_t)__cvta_generic_to_shared(sm);
    if (tid == 0) {
        asm volatile("mbarrier.init.shared.b64 [%0], 1;" :: "r"(mb) : "memory");
    }
    __syncthreads();
    if (tid == 0) {
        asm volatile("mbarrier.arrive.expect_tx.shared.b64 _, [%0], %1;"
                     :: "r"(mb), "r"((uint32_t)STAGE_BYTES_) : "memory");
        asm volatile(
            "cp.async.bulk.tensor.3d.shared::cta.global.tile.mbarrier::complete_tx::bytes "
            "[%0], [%1, {%2, %3, %4}], [%5];"
            :: "r"(sa), "l"(&tmap), "r"(xq), "r"(ymin), "r"(0), "r"(mb)
            : "memory");
    }

    // independent per-pixel coord setup overlaps with TMA flight
    const float fw = (float)(w0 + tx) + 0.5f;
    const float px = fmaf(t00, fw, cx);
    const float py = fmaf(t10, fw, cy);

    // wait for TMA completion (phase 0)
    {
        uint32_t done;
        asm volatile(
            "{\n\t.reg .pred p;\n\t"
            "mbarrier.try_wait.parity.acquire.cta.shared::cta.b64 p, [%1], 0;\n\t"
            "selp.b32 %0, 1, 0, p;\n\t}"
            : "=r"(done) : "r"(mb) : "memory");
        if (!done) {
            asm volatile(
                "{\n\t.reg .pred P1;\n\t"
                "WL_%=:\n\t"
                "mbarrier.try_wait.parity.acquire.cta.shared::cta.b64 P1, [%0], 0, 0x989680;\n\t"
                "@P1 bra.uni WD_%=;\n\t"
                "bra.uni WL_%=;\n\t"
                "WD_%=:\n\t}"
                :: "r"(mb) : "memory");
        }
    }

    // ---- unified sampling path (interior AND boundary; OOB corners are 0)
    #pragma unroll
    for (int k = 0; k < 4; ++k) {
        const int h = h0 + ty + (k << 3);
        const float fh = (float)h + 0.5f;
        const float ix = fmaf(t01, fh, px);
        const float iy = fmaf(t11, fh, py);

        const float x0f = floorf(ix);
        const float y0f = floorf(iy);
        const float wx1 = ix - x0f;
        const float wy1 = iy - y0f;

        const int x0 = (int)x0f;
        const int y0 = (int)y0f;
        const int base = (y0 - ymin) * BOXW_ + (x0 - xq);

        const float a00 = sm[base],         a10 = sm[base + 1];
        const float a01 = sm[base + BOXW_], a11 = sm[base + BOXW_ + 1];
        float u0 = fmaf(wx1, a10 - a00, a00);
        float u1 = fmaf(wx1, a11 - a01, a01);
        const float r0 = fmaf(wy1, u1 - u0, u0);

        const float b00 = sm[PLANE_ + base],         b10 = sm[PLANE_ + base + 1];
        const float b01 = sm[PLANE_ + base + BOXW_], b11 = sm[PLANE_ + base + BOXW_ + 1];
        u0 = fmaf(wx1, b10 - b00, b00);
        u1 = fmaf(wx1, b11 - b01, b01);
        const float r1 = fmaf(wy1, u1 - u0, u0);

        const float c00 = sm[2*PLANE_ + base],         c10 = sm[2*PLANE_ + base + 1];
        const float c01 = sm[2*PLANE_ + base + BOXW_], c11 = sm[2*PLANE_ + base + BOXW_ + 1];
        u0 = fmaf(wx1, c10 - c00, c00);
        u1 = fmaf(wx1, c11 - c01, c01);
        const float r2 = fmaf(wy1, u1 - u0, u0);

        // os = (wx0*vx0 + wx1*vx1) * (wy0*vy0 + wy1*vy1); ==1 when interior
        const float ex0 = ((unsigned)x0       < (unsigned)W_) ? (1.0f - wx1) : 0.f;
        const float ex1 = ((unsigned)(x0 + 1) < (unsigned)W_) ? wx1 : 0.f;
        const float ey0 = ((unsigned)y0       < (unsigned)H_) ? (1.0f - wy1) : 0.f;
        const float ey1 = ((unsigned)(y0 + 1) < (unsigned)H_) ? wy1 : 0.f;

        const size_t o = ((size_t)h << 10) + (w0 + tx);
        xs0[o] = r0; xs1[o] = r1; xs2[o] = r2;
        oso[o] = (ex0 + ex1) * (ey0 + ey1);
    }
}

extern "C" void kernel_launch(void* const* d_in, const int* in_sizes, int n_in,
                              void* d_out, int out_size) {
    const float* x = (const float*)d_in[0];        // (1,3,1024,1024)
    const float* A = (const float*)d_in[1];        // (1,12,2,3)
    float* out = (float*)d_out;

    // Encode tensor map host-side (runs only at capture; baked into the graph
    // node as a by-value __grid_constant__ param). No device allocation.
    typedef CUresult (*EncFn)(CUtensorMap*, CUtensorMapDataType, cuuint32_t,
                              void*, const cuuint64_t*, const cuuint64_t*,
                              const cuuint32_t*, const cuuint32_t*,
                              CUtensorMapInterleave, CUtensorMapSwizzle,
                              CUtensorMapL2promotion, CUtensorMapFloatOOBfill);
    void* sym = nullptr;
    cudaDriverEntryPointQueryResult qr;
    cudaGetDriverEntryPointByVersion("cuTensorMapEncodeTiled", &sym, 12000,
                                     cudaEnableDefault, &qr);

    CUtensorMap tmap;
    cuuint64_t dims[3]    = {W_, H_, 3};
    cuuint64_t strides[2] = {W_ * 4ull, (cuuint64_t)HW_ * 4ull};
    cuuint32_t box[3]     = {BOXW_, BOXH_, 3};
    cuuint32_t es[3]      = {1, 1, 1};
    ((EncFn)sym)(&tmap, CU_TENSOR_MAP_DATA_TYPE_FLOAT32, 3, (void*)x,
                 dims, strides, box, es,
                 CU_TENSOR_MAP_INTERLEAVE_NONE, CU_TENSOR_MAP_SWIZZLE_NONE,
                 CU_TENSOR_MAP_L2_PROMOTION_L2_128B,
                 CU_TENSOR_MAP_FLOAT_OOB_FILL_NONE);

    dim3 grid(W_ / 32, H_ / 32, NTR_);
    sample_tile_tma<<<grid, 256>>>(x, A, out, tmap);
}